// round 4
// baseline (speedup 1.0000x reference)
#include <cuda_runtime.h>
#include <cstdint>

// Gather-and-concat:
//   out[b, 0:512]    = lstm1[b, input_length[b]-1, :]
//   out[b, 512:1024] = lstm2[b, support_length[b]-1, :]
// B=64, T=2048, H=512, fp32.
//
// NOTE: the reference asks for jnp.int64 lengths, but JAX without x64 mode
// silently downcasts to int32 — so the length arrays arrive as int32.
// Row index is clamped defensively so any residual dtype mismatch surfaces
// as a rel_err, never as an illegal access.
//
// Launch: 128 CTAs (blockIdx.x = b*2 + src), 128 threads; each thread moves
// one float4 (H=512 floats = 128 float4s). Single wave on 148 SMs.

static constexpr int B = 64;
static constexpr int T = 2048;
static constexpr int H = 512;

__global__ __launch_bounds__(128, 1)
void vlos_gather_kernel(const float4* __restrict__ lstm1,
                        const float4* __restrict__ lstm2,
                        const int* __restrict__ input_length,
                        const int* __restrict__ support_length,
                        float4* __restrict__ out)
{
    const int blk = blockIdx.x;        // 0..127
    const int b   = blk >> 1;          // batch
    const int src = blk & 1;           // 0 = lstm1, 1 = lstm2

    // Per-CTA scalar index load (uniform across threads -> broadcast).
    int row = (src ? support_length[b] : input_length[b]) - 1;
    // Defensive clamp: wrong dtype shows as rel_err, not a crash.
    row = max(0, min(T - 1, row));

    const float4* base = src ? lstm2 : lstm1;
    // Row base in float4 units: (b*T + row) * (H/4)
    const size_t src_off = ((size_t)b * T + (size_t)row) * (H / 4);
    // Output: row b has 2*H floats = 2*H/4 float4s; src selects half.
    const size_t dst_off = (size_t)b * (2 * H / 4) + (size_t)src * (H / 4);

    const int t = threadIdx.x;         // 0..127, exactly H/4 threads
    out[dst_off + t] = base[src_off + t];
}

extern "C" void kernel_launch(void* const* d_in, const int* in_sizes, int n_in,
                              void* d_out, int out_size)
{
    const float4* lstm1 = (const float4*)d_in[0];
    const float4* lstm2 = (const float4*)d_in[1];
    const int*    ilen  = (const int*)d_in[2];
    const int*    slen  = (const int*)d_in[3];
    float4*       out   = (float4*)d_out;

    vlos_gather_kernel<<<B * 2, H / 4>>>(lstm1, lstm2, ilen, slen, out);
}

// round 5
// speedup vs baseline: 1.5000x; 1.5000x over previous
#include <cuda_runtime.h>
#include <cstdint>

// Gather-and-concat:
//   out[b, 0:512]    = lstm1[b, input_length[b]-1, :]
//   out[b, 512:1024] = lstm2[b, support_length[b]-1, :]
// B=64, T=2048, H=512, fp32. Lengths arrive as int32 (JAX silently downcasts
// the reference's int64 without x64 mode).
//
// Latency-bound: total traffic is 512 KB (0.7% of HBM in the prior round).
// Structure targets the fixed-overhead floor: ONE kernel, ONE wave,
// 64 CTAs x 256 threads (one CTA per batch; threads 0-127 -> lstm1 half,
// 128-255 -> lstm2 half). Both length loads issue immediately so the two
// dependent gather chains overlap inside the CTA.

static constexpr int B = 64;
static constexpr int T = 2048;
static constexpr int H = 512;

__global__ __launch_bounds__(256, 1)
void vlos_gather_kernel(const float4* __restrict__ lstm1,
                        const float4* __restrict__ lstm2,
                        const int* __restrict__ input_length,
                        const int* __restrict__ support_length,
                        float4* __restrict__ out)
{
    const int b   = blockIdx.x;          // batch 0..63
    const int t   = threadIdx.x;         // 0..255
    const int src = t >> 7;              // 0 = lstm1 half, 1 = lstm2 half
    const int col = t & 127;             // float4 column within the 512-float row

    // Per-half uniform length load; issued without cross-half dependency so
    // both gather chains start in parallel.
    int row = (src ? support_length[b] : input_length[b]) - 1;
    row = max(0, min(T - 1, row));       // defensive: dtype surprises -> rel_err, not crash

    const float4* base = src ? lstm2 : lstm1;
    const size_t src_off = ((size_t)b * T + (size_t)row) * (H / 4);
    // Output row b = 2*H floats = 256 float4s; src selects the half.
    const size_t dst_off = (size_t)b * (2 * H / 4) + (size_t)src * (H / 4);

    out[dst_off + col] = base[src_off + col];
}

extern "C" void kernel_launch(void* const* d_in, const int* in_sizes, int n_in,
                              void* d_out, int out_size)
{
    const float4* lstm1 = (const float4*)d_in[0];
    const float4* lstm2 = (const float4*)d_in[1];
    const int*    ilen  = (const int*)d_in[2];
    const int*    slen  = (const int*)d_in[3];
    float4*       out   = (float4*)d_out;

    vlos_gather_kernel<<<B, 256>>>(lstm1, lstm2, ilen, slen, out);
}

// round 6
// speedup vs baseline: 1.5105x; 1.0070x over previous
#include <cuda_runtime.h>
#include <cstdint>

// Gather-and-concat:
//   out[b, 0:512]    = lstm1[b, input_length[b]-1, :]
//   out[b, 512:1024] = lstm2[b, support_length[b]-1, :]
// B=64, T=2048, H=512, fp32. Lengths arrive as int32 (JAX silently downcasts
// the reference's int64 without x64 mode).
//
// Latency-bound at the launch-overhead floor: total traffic 512 KB (<1% HBM),
// body = len-LDG -> gather-LDG -> STG dependent chain (~0.7us), rest is fixed
// overhead. One kernel, one wave: 64 CTAs (one per batch) x 256 threads
// (threads 0-127 -> lstm1 half, 128-255 -> lstm2 half), one float4/thread.
// All indexing is 32-bit (max offset 16.7M float4s < 2^31) to keep the SASS
// prologue to a handful of IMADs ahead of the memory chain.

static constexpr int B = 64;
static constexpr int T = 2048;
static constexpr int H = 512;

__global__ __launch_bounds__(256, 1)
void vlos_gather_kernel(const float4* __restrict__ lstm1,
                        const float4* __restrict__ lstm2,
                        const int* __restrict__ input_length,
                        const int* __restrict__ support_length,
                        float4* __restrict__ out)
{
    const int b   = blockIdx.x;          // batch 0..63
    const int t   = threadIdx.x;         // 0..255
    const int src = t >> 7;              // 0 = lstm1 half, 1 = lstm2 half
    const int col = t & 127;             // float4 column within the 512-float row

    // Uniform per-half length load (warp-broadcast, single transaction).
    int row = __ldg(src ? &support_length[b] : &input_length[b]) - 1;
    row = max(0, min(T - 1, row));       // defensive: dtype surprises -> rel_err, not crash

    const float4* base = src ? lstm2 : lstm1;
    // 32-bit offsets: (b*T + row) * 128 <= 16.7M, well inside int range.
    const int src_off = (b * T + row) * (H / 4) + col;
    const int dst_off = b * (2 * H / 4) + src * (H / 4) + col;

    out[dst_off] = __ldg(&base[src_off]);
}

extern "C" void kernel_launch(void* const* d_in, const int* in_sizes, int n_in,
                              void* d_out, int out_size)
{
    const float4* lstm1 = (const float4*)d_in[0];
    const float4* lstm2 = (const float4*)d_in[1];
    const int*    ilen  = (const int*)d_in[2];
    const int*    slen  = (const int*)d_in[3];
    float4*       out   = (float4*)d_out;

    vlos_gather_kernel<<<B, 256>>>(lstm1, lstm2, ilen, slen, out);
}